// round 2
// baseline (speedup 1.0000x reference)
#include <cuda_runtime.h>

#define HID   100
#define G4    400      // 4 * HID
#define SEQ   8192
#define NCLS  20
#define TPB   16       // timesteps per block in xproj kernel

// 13.1 MB scratch for x_proj (allowed: __device__ global, no allocation)
__device__ float g_xproj[SEQ * G4];

// ---------- packed f32x2 helpers (sm_100+) ----------
__device__ __forceinline__ unsigned long long ffma2(unsigned long long a,
                                                    unsigned long long b,
                                                    unsigned long long c) {
    unsigned long long d;
    asm("fma.rn.f32x2 %0, %1, %2, %3;" : "=l"(d) : "l"(a), "l"(b), "l"(c));
    return d;
}
__device__ __forceinline__ unsigned long long pack2(float x, float y) {
    unsigned long long v;
    asm("mov.b64 %0, {%1, %2};" : "=l"(v) : "f"(x), "f"(y));
    return v;
}
__device__ __forceinline__ float2 unpack2(unsigned long long v) {
    float2 f;
    asm("mov.b64 {%0, %1}, %2;" : "=f"(f.x), "=f"(f.y) : "l"(v));
    return f;
}

__device__ __forceinline__ float sigmoid_f(float x) {
    return 1.0f / (1.0f + __expf(-x));
}
__device__ __forceinline__ float tanh_f(float x) {
    return 2.0f / (1.0f + __expf(-2.0f * x)) - 1.0f;
}

// ---------------------------------------------------------------------------
// Kernel 1: x_proj[t][j] = emb[seq[t]] . W_ih[j] + b_ih[j] + b_hh[j]
// Grid-parallel: 512 blocks x 16 timesteps. W_ih row held in registers.
// ---------------------------------------------------------------------------
__global__ __launch_bounds__(416, 1)
void xproj_kernel(const int* __restrict__ seq,
                  const float* __restrict__ emb,
                  const float* __restrict__ Wih,
                  const float* __restrict__ bih,
                  const float* __restrict__ bhh)
{
    __shared__ __align__(16) float se[TPB][HID];
    const int t0  = blockIdx.x * TPB;
    const int tid = threadIdx.x;

    // gather embeddings for this block's 16 timesteps
    for (int idx = tid; idx < TPB * HID; idx += blockDim.x) {
        int t = idx / HID;
        int k = idx - t * HID;
        se[t][k] = emb[(long long)seq[t0 + t] * HID + k];
    }
    __syncthreads();

    if (tid < G4) {
        float4 w[25];
        const float4* wr = reinterpret_cast<const float4*>(Wih + tid * HID);
#pragma unroll
        for (int q = 0; q < 25; q++) w[q] = wr[q];
        const float bias = bih[tid] + bhh[tid];

        for (int t = 0; t < TPB; t++) {
            const float4* hv = reinterpret_cast<const float4*>(se[t]);
            float a0 = 0.f, a1 = 0.f, a2 = 0.f, a3 = 0.f;
#pragma unroll
            for (int q = 0; q < 25; q++) {
                float4 h4 = hv[q];
                a0 = fmaf(w[q].x, h4.x, a0);
                a1 = fmaf(w[q].y, h4.y, a1);
                a2 = fmaf(w[q].z, h4.z, a2);
                a3 = fmaf(w[q].w, h4.w, a3);
            }
            g_xproj[(t0 + t) * G4 + tid] = (a0 + a1) + (a2 + a3) + bias;
        }
    }
}

// ---------------------------------------------------------------------------
// Kernel 2: persistent single-block LSTM recurrence + final FC.
// 448 threads. Threads 0..399: one gate row each, W_hh row in 50 f32x2 regs.
// Threads 0..99 additionally own c[j] in a register and do the cell update.
// ---------------------------------------------------------------------------
__global__ __launch_bounds__(448, 1)
void lstm_kernel(const float* __restrict__ Whh,
                 const float* __restrict__ fcw,
                 const float* __restrict__ fcb,
                 float* __restrict__ out)
{
    __shared__ __align__(16) float sh_h[HID];
    __shared__ float sh_act[G4];

    const int tid = threadIdx.x;

    // preload W_hh row into registers as packed f32x2 pairs
    unsigned long long w[50];
    if (tid < G4) {
        const float4* wr = reinterpret_cast<const float4*>(Whh + tid * HID);
#pragma unroll
        for (int q = 0; q < 25; q++) {
            float4 v = wr[q];
            w[2 * q]     = pack2(v.x, v.y);
            w[2 * q + 1] = pack2(v.z, v.w);
        }
    }
    if (tid < HID) sh_h[tid] = 0.0f;
    float c = 0.0f;
    __syncthreads();

    for (int t = 0; t < SEQ; t++) {
        if (tid < G4) {
            // issue xp load early; consumed only at the end of the GEMV,
            // so its L2 latency hides under ~400 cycles of FFMA2 issue.
            const float xv = g_xproj[t * G4 + tid];

            const ulonglong2* hp = reinterpret_cast<const ulonglong2*>(sh_h);
            unsigned long long a0 = 0ull, a1 = 0ull, a2 = 0ull, a3 = 0ull;
#pragma unroll
            for (int q = 0; q < 25; q++) {
                ulonglong2 hv = hp[q];           // broadcast LDS.128
                if (q & 1) {
                    a2 = ffma2(w[2 * q],     hv.x, a2);
                    a3 = ffma2(w[2 * q + 1], hv.y, a3);
                } else {
                    a0 = ffma2(w[2 * q],     hv.x, a0);
                    a1 = ffma2(w[2 * q + 1], hv.y, a1);
                }
            }
            float2 f0 = unpack2(a0), f1 = unpack2(a1);
            float2 f2 = unpack2(a2), f3 = unpack2(a3);
            float gate = ((f0.x + f0.y) + (f1.x + f1.y)) +
                         ((f2.x + f2.y) + (f3.x + f3.y)) + xv;

            // PyTorch gate order: i(0..99) f(100..199) g(200..299) o(300..399)
            float act = (tid >= 2 * HID && tid < 3 * HID) ? tanh_f(gate)
                                                          : sigmoid_f(gate);
            sh_act[tid] = act;
        }
        __syncthreads();

        if (tid < HID) {
            float iv = sh_act[tid];
            float fv = sh_act[HID + tid];
            float gv = sh_act[2 * HID + tid];
            float ov = sh_act[3 * HID + tid];
            c = fmaf(fv, c, iv * gv);
            sh_h[tid] = ov * tanh_f(c);
        }
        __syncthreads();
    }

    // final FC: out[n] = h_last . fc_w[n] + fc_b[n]
    if (tid < NCLS) {
        float s = fcb[tid];
        const float* wr = fcw + tid * HID;
#pragma unroll 4
        for (int k = 0; k < HID; k++) s = fmaf(wr[k], sh_h[k], s);
        out[tid] = s;
    }
}

// ---------------------------------------------------------------------------
extern "C" void kernel_launch(void* const* d_in, const int* in_sizes, int n_in,
                              void* d_out, int out_size)
{
    const int*   seq = (const int*)  d_in[0];
    const float* emb = (const float*)d_in[1];
    const float* Wih = (const float*)d_in[2];
    const float* Whh = (const float*)d_in[3];
    const float* bih = (const float*)d_in[4];
    const float* bhh = (const float*)d_in[5];
    const float* fcw = (const float*)d_in[6];
    const float* fcb = (const float*)d_in[7];

    xproj_kernel<<<SEQ / TPB, 416>>>(seq, emb, Wih, bih, bhh);
    lstm_kernel<<<1, 448>>>(Whh, fcw, fcb, (float*)d_out);
}